// round 11
// baseline (speedup 1.0000x reference)
#include <cuda_runtime.h>

// Cox partial-likelihood loss, n = 8192, sort + suffix-scan algorithm.
// loss = -mean_i[ (theta_i - log(sum_{j: t_j>=t_i} exp(theta_j) + eps)) * e_i ]
//
// S_i = sum_{j: t_j >= t_i} exp(theta_j) is a suffix sum over t-sorted order.
//
// K1 (16 blocks x 512): hybrid bitonic sort of each 512-chunk of
//     (t, exp(risk)) -- j<32 stages via register shfl_xor, j>=32 via smem --
//     then warp-shuffle suffix scan. Stores sorted-t + suffix(+sentinel).
//     Fixed comparator network -> deterministic.
//
// K2 (grid 16x16, 256 thr): thread = TWO (i, chunk) searches (independent
//     chains -> ILP to hide the dependent-LDS binary-search latency that
//     bounded the previous round: occ 41%, issue 11%). Stages the 2KB
//     sorted-t chunk + suffix table in smem, runs 2 interleaved 10-step
//     branchless lower_bounds, writes 2 partials. Election: last of the 16
//     chunk-blocks per 512-i tile sums 16 partials per i in fixed order
//     (32 independent LDGs/thread -> MLP), applies log/event mask,
//     block-reduces; global election writes -sum/n, resets counters.
//
// No device allocations, no fp atomics, graph-capturable, deterministic.

#define N        8192
#define CHUNK    512
#define NCHUNK   16            // N / CHUNK
#define K1_BLOCK 512
#define K2_BLOCK 256
#define IPT      2             // i's per K2 thread
#define TILE     (K2_BLOCK * IPT)   // 512 i's per tile
#define NTILE    (N / TILE)         // 16
#define EPS_F    1e-8f

__device__ float g_tsorted[N];                    // chunk-sorted t
__device__ float g_sfx[NCHUNK * (CHUNK + 1)];     // suffix sums + sentinel
__device__ float g_partS[NCHUNK * N];             // [chunk][i] partials
__device__ float g_bsum[NTILE];
__device__ int   g_done_it[NTILE];                // zero-init
__device__ int   g_done_final;                    // zero-init

// in-warp bitonic compare-exchange stage (j < 32)
__device__ __forceinline__ void bstage_shfl(float& key, float& val,
                                            int j, int k, int tid) {
    const float bk = __shfl_xor_sync(0xffffffffu, key, j);
    const float bv = __shfl_xor_sync(0xffffffffu, val, j);
    const bool lower = (tid & j) == 0;
    const bool up    = (tid & k) == 0;
    const bool take_b = (up == lower) ? (bk < key) : (bk > key);
    if (take_b) { key = bk; val = bv; }
}

// ---------------------------------------------------------------- K1
__global__ __launch_bounds__(K1_BLOCK) void cox_sort_kernel(
    const float* __restrict__ risk,
    const float* __restrict__ t)
{
    __shared__ float sk[CHUNK];
    __shared__ float sv[CHUNK];
    __shared__ float wsum[K1_BLOCK / 32];

    const int tid  = threadIdx.x;
    const int lane = tid & 31;
    const int w    = tid >> 5;
    const int base = blockIdx.x * CHUNK;

    float key = t[base + tid];
    float val = expf(risk[base + tid]);

    // phases k = 2..32: entirely in registers (15 shfl stages, no barriers)
#pragma unroll
    for (int k = 2; k <= 32; k <<= 1)
#pragma unroll
        for (int j = k >> 1; j >= 1; j >>= 1)
            bstage_shfl(key, val, j, k, tid);

    // phases k = 64..512: j>=32 via smem, j<32 via shfl
    for (int k = 64; k <= CHUNK; k <<= 1) {
        for (int j = k >> 1; j >= 32; j >>= 1) {
            sk[tid] = key; sv[tid] = val;
            __syncthreads();
            const int p = tid ^ j;
            const float bk = sk[p], bv = sv[p];
            const bool lower = (tid & j) == 0;
            const bool up    = (tid & k) == 0;
            const bool take_b = (up == lower) ? (bk < key) : (bk > key);
            if (take_b) { key = bk; val = bv; }
            __syncthreads();
        }
#pragma unroll
        for (int j = 16; j >= 1; j >>= 1)
            bstage_shfl(key, val, j, k, tid);
    }

    // inclusive suffix scan of val: warp shfl scan + cross-warp fixup
    float v = val;
#pragma unroll
    for (int off = 1; off < 32; off <<= 1) {
        const float x = __shfl_down_sync(0xffffffffu, v, off);
        if (lane + off < 32) v += x;
    }
    if (lane == 0) wsum[w] = v;
    __syncthreads();
    float add = 0.0f;
    for (int ww = w + 1; ww < K1_BLOCK / 32; ww++)   // fixed order
        add += wsum[ww];
    v += add;

    g_tsorted[base + tid] = key;
    g_sfx[blockIdx.x * (CHUNK + 1) + tid] = v;
    if (tid == 0)
        g_sfx[blockIdx.x * (CHUNK + 1) + CHUNK] = 0.0f;   // sentinel
}

// ---------------------------------------------------------------- K2
__global__ __launch_bounds__(K2_BLOCK) void cox_search_kernel(
    const float* __restrict__ risk,
    const float* __restrict__ t,
    const float* __restrict__ e,
    float* __restrict__ out,
    int n)
{
    __shared__ float ts[CHUNK];
    __shared__ float sf[CHUNK + 1];
    __shared__ float red[K2_BLOCK];
    __shared__ int   flag;

    const int c   = blockIdx.x;     // chunk    0..15
    const int ib  = blockIdx.y;     // i-tile   0..15
    const int tid = threadIdx.x;

    // stage this chunk's sorted-t and suffix table (coalesced)
    for (int idx = tid; idx < CHUNK; idx += K2_BLOCK)
        ts[idx] = g_tsorted[c * CHUNK + idx];
    for (int idx = tid; idx < CHUNK + 1; idx += K2_BLOCK)
        sf[idx] = g_sfx[c * (CHUNK + 1) + idx];
    __syncthreads();

    const int i0 = ib * TILE + tid;            // two i's per thread
    const int i1 = i0 + K2_BLOCK;
    const float t0 = t[i0];
    const float t1 = t[i1];

    // two interleaved branchless lower_bounds (independent chains -> ILP)
    int p0 = 0, p1 = 0;
#pragma unroll
    for (int bit = CHUNK >> 1; bit >= 1; bit >>= 1) {
        const float a0 = ts[p0 + bit - 1];
        const float a1 = ts[p1 + bit - 1];
        if (a0 < t0) p0 += bit;
        if (a1 < t1) p1 += bit;
    }
    if (ts[p0] < t0) p0++;                     // allow pos == CHUNK
    if (ts[p1] < t1) p1++;

    g_partS[c * n + i0] = sf[p0];
    g_partS[c * n + i1] = sf[p1];

    // ---- elect last chunk-block of this i-tile
    __threadfence();
    __syncthreads();
    if (tid == 0)
        flag = (atomicAdd(&g_done_it[ib], 1) == NCHUNK - 1);
    __syncthreads();
    if (!flag) return;

    __threadfence();   // acquire: all 16 partials for this tile visible

    // finalize: S for both i's, 32 independent LDGs (fixed order per i)
    float S0 = 0.0f, S1 = 0.0f;
#pragma unroll
    for (int cc = 0; cc < NCHUNK; cc++) {
        S0 += __ldcg(&g_partS[cc * n + i0]);
        S1 += __ldcg(&g_partS[cc * n + i1]);
    }

    float acc = (risk[i0] - logf(S0 + EPS_F)) * e[i0]
              + (risk[i1] - logf(S1 + EPS_F)) * e[i1];

    // fixed-order block reduction of 256 values
    red[tid] = acc;
    __syncthreads();
    if (tid < 128) red[tid] += red[tid + 128];
    __syncthreads();
    if (tid < 64)  red[tid] += red[tid + 64];
    __syncthreads();
    if (tid < 32) {
        float v = red[tid] + red[tid + 32];
#pragma unroll
        for (int off = 16; off > 0; off >>= 1)
            v += __shfl_down_sync(0xffffffffu, v, off);

        if (tid == 0) {
            g_bsum[ib] = v;
            __threadfence();
            if (atomicAdd(&g_done_final, 1) == NTILE - 1) {
                __threadfence();
                float total = 0.0f;
                for (int b = 0; b < NTILE; b++)       // fixed order
                    total += __ldcg(&g_bsum[b]);
                out[0] = -total / (float)n;

                // reset counters for next graph replay
                g_done_final = 0;
                for (int b = 0; b < NTILE; b++) g_done_it[b] = 0;
                __threadfence();
            }
        }
    }
}

// ---------------------------------------------------------------- launch
extern "C" void kernel_launch(void* const* d_in, const int* in_sizes, int n_in,
                              void* d_out, int out_size) {
    const float* risk = (const float*)d_in[0];
    const float* t    = (const float*)d_in[1];
    const float* e    = (const float*)d_in[2];
    float* out = (float*)d_out;

    const int n = in_sizes[0];   // 8192

    cox_sort_kernel<<<NCHUNK, K1_BLOCK>>>(risk, t);
    cox_search_kernel<<<dim3(NCHUNK, NTILE), K2_BLOCK>>>(risk, t, e, out, n);
}